// round 5
// baseline (speedup 1.0000x reference)
#include <cuda_runtime.h>
#include <cuda_fp16.h>
#include <cstdint>

#define BATCH 65536
#define NP 320
#define BM 64
#define BN 64
#define BK 32
#define LDA_S 40
#define LDB_S 72

__device__ __align__(16) __half g_Wt [768  * NP];
__device__ __align__(16) __half g_Wim[2048 * NP];
__device__ __align__(16) __half g_A  [3 * NP * NP];
__device__ float g_C[3];
__device__ __align__(16) float g_P[3][(size_t)BATCH * NP];  // T, IM, CD
__device__ __align__(16) float g_Y[3][(size_t)BATCH * NP];  // T, IM, CD

static __device__ __forceinline__ uint32_t su32(const void* p) {
    return (uint32_t)__cvta_generic_to_shared(p);
}
static __device__ __forceinline__ void ldsm4(uint32_t* r, uint32_t a) {
    asm volatile("ldmatrix.sync.aligned.m8n8.x4.shared.b16 {%0,%1,%2,%3}, [%4];\n"
                 : "=r"(r[0]), "=r"(r[1]), "=r"(r[2]), "=r"(r[3]) : "r"(a));
}
static __device__ __forceinline__ void ldsm4t(uint32_t* r, uint32_t a) {
    asm volatile("ldmatrix.sync.aligned.m8n8.x4.trans.shared.b16 {%0,%1,%2,%3}, [%4];\n"
                 : "=r"(r[0]), "=r"(r[1]), "=r"(r[2]), "=r"(r[3]) : "r"(a));
}
static __device__ __forceinline__ void mma16816(float* c, const uint32_t* a, const uint32_t* b) {
    asm volatile("mma.sync.aligned.m16n8k16.row.col.f32.f16.f16.f32 "
                 "{%0,%1,%2,%3}, {%4,%5,%6,%7}, {%8,%9}, {%0,%1,%2,%3};\n"
                 : "+f"(c[0]), "+f"(c[1]), "+f"(c[2]), "+f"(c[3])
                 : "r"(a[0]), "r"(a[1]), "r"(a[2]), "r"(a[3]), "r"(b[0]), "r"(b[1]));
}

// ---- convert weight [K x 300] fp32 -> [K x NP] fp16 (zero-padded) ----
__global__ void k_convW(const float* __restrict__ src, int which, int K) {
    __half* dst = which ? g_Wim : g_Wt;
    int i = blockIdx.x * 256 + threadIdx.x;
    if (i < K * NP) {
        int k = i / NP, n = i - k * NP;
        dst[i] = __float2half_rn(n < 300 ? src[k * 300 + n] : 0.f);
    }
}

// ---- A[b][i][j] = Wq[i,:]·Wk[j,:]  (i,j<300 else 0) ----
__global__ void k_prepA(const float* __restrict__ Wq, const float* __restrict__ Wk, int b) {
    __shared__ float sq[16][17], sk[16][17];
    int tx = threadIdx.x, ty = threadIdx.y;
    int i = blockIdx.y * 16 + ty, j = blockIdx.x * 16 + tx;
    int jr = blockIdx.x * 16 + ty;
    float a = 0.f;
    for (int o0 = 0; o0 < 300; o0 += 16) {
        int o = o0 + tx;
        sq[ty][tx] = (i  < 300 && o < 300) ? Wq[i  * 300 + o] : 0.f;
        sk[ty][tx] = (jr < 300 && o < 300) ? Wk[jr * 300 + o] : 0.f;
        __syncthreads();
        #pragma unroll
        for (int t = 0; t < 16; t++) a += sq[ty][t] * sk[tx][t];
        __syncthreads();
    }
    float v = (i < 300 && j < 300) ? a : 0.f;
    if (i < NP && j < NP) g_A[(size_t)b * NP * NP + i * NP + j] = __float2half_rn(v);
}

// ---- u_i = Wq[i]·bk + Wk[i]·bq -> A[b][i][300];  block 300: c = bq·bk ----
__global__ void k_u(const float* __restrict__ Wq, const float* __restrict__ Wk,
                    const float* __restrict__ bq, const float* __restrict__ bk, int b) {
    __shared__ float red[2];
    int i = blockIdx.x, tid = threadIdx.x;
    float s = 0.f;
    if (i < 300) { for (int o = tid; o < 300; o += 64) s += Wq[i*300+o]*bk[o] + Wk[i*300+o]*bq[o]; }
    else         { for (int o = tid; o < 300; o += 64) s += bq[o]*bk[o]; }
    #pragma unroll
    for (int o = 16; o; o >>= 1) s += __shfl_xor_sync(0xffffffffu, s, o);
    if ((tid & 31) == 0) red[tid >> 5] = s;
    __syncthreads();
    if (tid == 0) {
        float tot = red[0] + red[1];
        if (i < 300) g_A[(size_t)b * NP * NP + i * NP + 300] = __float2half_rn(tot);
        else         g_C[b] = tot;
    }
}

// ---- generic GEMM: C[BATCH x NP] = X[BATCH x K](fp32) @ W[K x NP](fp16) + bias ----
__global__ void __launch_bounds__(128) k_gemm(
    const float* __restrict__ Xin, int xsel, int lda,
    int wsel, int K, const float* __restrict__ bias, int csel)
{
    const float* X = (xsel < 0) ? Xin : g_P[xsel];
    const __half* W = (wsel == 0) ? g_Wt : (wsel == 1) ? g_Wim
                      : g_A + (size_t)(wsel - 2) * NP * NP;
    float* Cout = (csel < 3) ? g_P[csel] : g_Y[csel - 3];

    __shared__ __half sA[BM * LDA_S], sB[BK * LDB_S];
    int tid = threadIdx.x, wid = tid >> 5, lane = tid & 31;
    int m0 = blockIdx.y * BM, n0 = blockIdx.x * BN;
    int wm = (wid >> 1) * 32, wn = (wid & 1) * 32;
    float acc[2][4][4];
    #pragma unroll
    for (int i = 0; i < 2; i++)
        #pragma unroll
        for (int j = 0; j < 4; j++)
            #pragma unroll
            for (int t = 0; t < 4; t++) acc[i][j][t] = 0.f;

    for (int k0 = 0; k0 < K; k0 += BK) {
        #pragma unroll
        for (int it = 0; it < 4; it++) {
            int idx = (it * 128 + tid) * 4;
            int r = idx >> 5, c = idx & 31;
            float4 v = *(const float4*)(X + (size_t)(m0 + r) * lda + k0 + c);
            __half2* d = (__half2*)(sA + r * LDA_S + c);
            d[0] = __floats2half2_rn(v.x, v.y);
            d[1] = __floats2half2_rn(v.z, v.w);
        }
        #pragma unroll
        for (int it = 0; it < 2; it++) {
            int idx = (it * 128 + tid) * 8;
            int r = idx >> 6, c = idx & 63;
            *(int4*)(sB + r * LDB_S + c) = *(const int4*)(W + (size_t)(k0 + r) * NP + n0 + c);
        }
        __syncthreads();
        #pragma unroll
        for (int kk = 0; kk < BK; kk += 16) {
            uint32_t af[2][4], bf[2][4];
            #pragma unroll
            for (int i = 0; i < 2; i++)
                ldsm4(af[i], su32(sA + (wm + i*16 + (lane & 15)) * LDA_S + kk + ((lane >> 4) << 3)));
            #pragma unroll
            for (int j = 0; j < 2; j++)
                ldsm4t(bf[j], su32(sB + (kk + (lane & 15)) * LDB_S + wn + j*16 + ((lane >> 4) << 3)));
            #pragma unroll
            for (int i = 0; i < 2; i++)
                #pragma unroll
                for (int j = 0; j < 2; j++) {
                    mma16816(acc[i][j*2+0], af[i], &bf[j][0]);
                    mma16816(acc[i][j*2+1], af[i], &bf[j][2]);
                }
        }
        __syncthreads();
    }
    int row = lane >> 2, col = (lane & 3) * 2;
    #pragma unroll
    for (int i = 0; i < 2; i++)
        #pragma unroll
        for (int j = 0; j < 4; j++) {
            int c = n0 + wn + j * 8 + col;
            float b0 = (bias && c   < 300) ? bias[c]   : 0.f;
            float b1 = (bias && c+1 < 300) ? bias[c+1] : 0.f;
            #pragma unroll
            for (int h = 0; h < 2; h++) {
                int r = m0 + wm + i * 16 + row + h * 8;
                Cout[(size_t)r * NP + c]     = acc[i][j][h*2]   + b0;
                Cout[(size_t)r * NP + c + 1] = acc[i][j][h*2+1] + b1;
            }
        }
}

// ---- per-row epilogue: dots, sigmoid, softmax, outputs ----
__global__ void k_final(float* __restrict__ out) {
    int r = blockIdx.x * 8 + (threadIdx.x >> 5);
    int lane = threadIdx.x & 31;
    const float* pT = g_P[0] + (size_t)r * NP;
    const float* pI = g_P[1] + (size_t)r * NP;
    const float* pC = g_P[2] + (size_t)r * NP;
    const float* yT = g_Y[0] + (size_t)r * NP;
    const float* yI = g_Y[1] + (size_t)r * NP;
    const float* yC = g_Y[2] + (size_t)r * NP;
    float dT = 0.f, dI = 0.f, dC = 0.f;
    for (int n = lane; n < 300; n += 32) {
        dT += yT[n] * pT[n]; dI += yI[n] * pI[n]; dC += yC[n] * pC[n];
    }
    #pragma unroll
    for (int o = 16; o; o >>= 1) {
        dT += __shfl_xor_sync(0xffffffffu, dT, o);
        dI += __shfl_xor_sync(0xffffffffu, dI, o);
        dC += __shfl_xor_sync(0xffffffffu, dC, o);
    }
    float is = rsqrtf(300.f);
    float aT = (dT + yT[300] + g_C[0]) * is;
    float aI = (dI + yI[300] + g_C[1]) * is;
    float aC = (dC + yC[300] + g_C[2]) * is;
    float zT = 1.f / (1.f + expf(-aT));
    float zI = 1.f / (1.f + expf(-aI));
    float zC = 1.f / (1.f + expf(-aC));
    float m0 = zI * zT, m1 = zC * zT;
    float mx = fmaxf(m0, m1);
    float e0 = expf(m0 - mx), e1 = expf(m1 - mx);
    float a0 = e0 / (e0 + e1), a1 = e1 / (e0 + e1);
    float* oT = out + (size_t)r * 300;
    float* oI = out + ((size_t)BATCH + r) * 300;
    float* oC = out + ((size_t)2 * BATCH + r) * 300;
    for (int n = lane; n < 300; n += 32) {
        oT[n] = pT[n];
        oI[n] = a0 * pI[n];
        oC[n] = a1 * pC[n];
    }
}

extern "C" void kernel_launch(void* const* d_in, const int* in_sizes, int n_in,
                              void* d_out, int out_size) {
    const float* T   = (const float*)d_in[0];
    const float* IM  = (const float*)d_in[1];
    const float* CD  = (const float*)d_in[2];
    const float* Wt  = (const float*)d_in[3];
    const float* bt  = (const float*)d_in[4];
    const float* Wim = (const float*)d_in[5];
    const float* bim = (const float*)d_in[6];

    k_convW<<<(768  * NP + 255) / 256, 256>>>(Wt,  0, 768);
    k_convW<<<(2048 * NP + 255) / 256, 256>>>(Wim, 1, 2048);

    dim3 b16(16, 16), g20(NP / 16, NP / 16);
    // branch 0 = T, 1 = IM, 2 = CD
    k_prepA<<<g20, b16>>>((const float*)d_in[7],  (const float*)d_in[9],  0);
    k_prepA<<<g20, b16>>>((const float*)d_in[11], (const float*)d_in[13], 1);
    k_prepA<<<g20, b16>>>((const float*)d_in[15], (const float*)d_in[17], 2);
    k_u<<<301, 64>>>((const float*)d_in[7],  (const float*)d_in[9],
                     (const float*)d_in[8],  (const float*)d_in[10], 0);
    k_u<<<301, 64>>>((const float*)d_in[11], (const float*)d_in[13],
                     (const float*)d_in[12], (const float*)d_in[14], 1);
    k_u<<<301, 64>>>((const float*)d_in[15], (const float*)d_in[17],
                     (const float*)d_in[16], (const float*)d_in[18], 2);

    dim3 gg(NP / BN, BATCH / BM);
    // projections
    k_gemm<<<gg, 128>>>(T,  -1, 768,  0, 768,  bt,  0);   // P_T
    k_gemm<<<gg, 128>>>(IM, -1, 2048, 1, 2048, bim, 1);   // P_IM
    k_gemm<<<gg, 128>>>(CD, -1, 768,  0, 768,  bt,  2);   // P_CD
    // quadratic forms: Y_b = P_b @ A_b
    k_gemm<<<gg, 128>>>(nullptr, 0, NP, 2, NP, nullptr, 3);  // Y_T
    k_gemm<<<gg, 128>>>(nullptr, 1, NP, 3, NP, nullptr, 4);  // Y_IM
    k_gemm<<<gg, 128>>>(nullptr, 2, NP, 4, NP, nullptr, 5);  // Y_CD

    k_final<<<BATCH / 8, 256>>>((float*)d_out);
}

// round 6
// speedup vs baseline: 1.7461x; 1.7461x over previous
#include <cuda_runtime.h>
#include <cuda_fp16.h>
#include <cstdint>

#define BATCH 65536
#define NP 320

// proj GEMM tiling
#define PBM 128
#define PBN 160
#define PBK 64
#define SA_STR 72     // halves: 64 + 8 pad
#define SB_STR 168    // halves: 160 + 8 pad
#define PROJ_SMEM ((2*PBM*SA_STR + 2*PBK*SB_STR) * 2)   // 79872 B

// attention kernel smem layout (halves)
#define SP_STR 328    // 320 + 8 pad
#define ATT_SP   (128 * SP_STR)
#define ATT_AB   (NP * SA_STR)          // 320 x 72
#define ATT_SMEM ((2*ATT_SP + ATT_AB) * 2 + 3*128*4)

__device__ __align__(16) __half g_Wt [768  * NP];
__device__ __align__(16) __half g_Wim[2048 * NP];
__device__ __align__(16) __half g_A  [3 * NP * NP];
__device__ float g_C[3];
__device__ __align__(16) __half g_Ph[3][(size_t)BATCH * NP];

static __device__ __forceinline__ uint32_t su32(const void* p) {
    return (uint32_t)__cvta_generic_to_shared(p);
}
static __device__ __forceinline__ void cp16(__half* dst, const __half* src) {
    asm volatile("cp.async.cg.shared.global [%0], [%1], 16;\n" :: "r"(su32(dst)), "l"(src));
}
static __device__ __forceinline__ void cpcommit() { asm volatile("cp.async.commit_group;\n"); }
static __device__ __forceinline__ void cpwait0()  { asm volatile("cp.async.wait_group 0;\n"); }
static __device__ __forceinline__ void ldsm4(uint32_t* r, uint32_t a) {
    asm volatile("ldmatrix.sync.aligned.m8n8.x4.shared.b16 {%0,%1,%2,%3}, [%4];\n"
                 : "=r"(r[0]), "=r"(r[1]), "=r"(r[2]), "=r"(r[3]) : "r"(a));
}
static __device__ __forceinline__ void ldsm4t(uint32_t* r, uint32_t a) {
    asm volatile("ldmatrix.sync.aligned.m8n8.x4.trans.shared.b16 {%0,%1,%2,%3}, [%4];\n"
                 : "=r"(r[0]), "=r"(r[1]), "=r"(r[2]), "=r"(r[3]) : "r"(a));
}
static __device__ __forceinline__ void mma16816(float* c, const uint32_t* a, const uint32_t* b) {
    asm volatile("mma.sync.aligned.m16n8k16.row.col.f32.f16.f16.f32 "
                 "{%0,%1,%2,%3}, {%4,%5,%6,%7}, {%8,%9}, {%0,%1,%2,%3};\n"
                 : "+f"(c[0]), "+f"(c[1]), "+f"(c[2]), "+f"(c[3])
                 : "r"(a[0]), "r"(a[1]), "r"(a[2]), "r"(a[3]), "r"(b[0]), "r"(b[1]));
}

// ---- convert weight [K x 300] fp32 -> [K x NP] fp16 (zero-padded) ----
__global__ void k_convW(const float* __restrict__ src, int which, int K) {
    __half* dst = which ? g_Wim : g_Wt;
    int i = blockIdx.x * 256 + threadIdx.x;
    if (i < K * NP) {
        int k = i / NP, n = i - k * NP;
        dst[i] = __float2half_rn(n < 300 ? src[k * 300 + n] : 0.f);
    }
}

// ---- A[b][i][j] = Wq[i,:]·Wk[j,:]  (i,j<300 else 0), all 3 branches ----
__global__ void k_prepA(const float* __restrict__ Wq0, const float* __restrict__ Wk0,
                        const float* __restrict__ Wq1, const float* __restrict__ Wk1,
                        const float* __restrict__ Wq2, const float* __restrict__ Wk2) {
    int b = blockIdx.z;
    const float* Wq = (b == 0) ? Wq0 : (b == 1) ? Wq1 : Wq2;
    const float* Wk = (b == 0) ? Wk0 : (b == 1) ? Wk1 : Wk2;
    __shared__ float sq[16][17], sk[16][17];
    int tx = threadIdx.x, ty = threadIdx.y;
    int i = blockIdx.y * 16 + ty, j = blockIdx.x * 16 + tx;
    int jr = blockIdx.x * 16 + ty;
    float a = 0.f;
    for (int o0 = 0; o0 < 300; o0 += 16) {
        int o = o0 + tx;
        sq[ty][tx] = (i  < 300 && o < 300) ? Wq[i  * 300 + o] : 0.f;
        sk[ty][tx] = (jr < 300 && o < 300) ? Wk[jr * 300 + o] : 0.f;
        __syncthreads();
        #pragma unroll
        for (int t = 0; t < 16; t++) a += sq[ty][t] * sk[tx][t];
        __syncthreads();
    }
    float v = (i < 300 && j < 300) ? a : 0.f;
    g_A[(size_t)b * NP * NP + i * NP + j] = __float2half_rn(v);
}

// ---- u_i = Wq[i]·bk + Wk[i]·bq -> A[b][i][300];  block i==300: c=bq·bk ----
__global__ void k_u(const float* __restrict__ Wq0, const float* __restrict__ Wk0,
                    const float* __restrict__ bq0, const float* __restrict__ bk0,
                    const float* __restrict__ Wq1, const float* __restrict__ Wk1,
                    const float* __restrict__ bq1, const float* __restrict__ bk1,
                    const float* __restrict__ Wq2, const float* __restrict__ Wk2,
                    const float* __restrict__ bq2, const float* __restrict__ bk2) {
    int b = blockIdx.y;
    const float* Wq = (b == 0) ? Wq0 : (b == 1) ? Wq1 : Wq2;
    const float* Wk = (b == 0) ? Wk0 : (b == 1) ? Wk1 : Wk2;
    const float* bq = (b == 0) ? bq0 : (b == 1) ? bq1 : bq2;
    const float* bk = (b == 0) ? bk0 : (b == 1) ? bk1 : bk2;
    __shared__ float red[2];
    int i = blockIdx.x, tid = threadIdx.x;
    float s = 0.f;
    if (i < 300) { for (int o = tid; o < 300; o += 64) s += Wq[i*300+o]*bk[o] + Wk[i*300+o]*bq[o]; }
    else         { for (int o = tid; o < 300; o += 64) s += bq[o]*bk[o]; }
    #pragma unroll
    for (int o = 16; o; o >>= 1) s += __shfl_xor_sync(0xffffffffu, s, o);
    if ((tid & 31) == 0) red[tid >> 5] = s;
    __syncthreads();
    if (tid == 0) {
        float tot = red[0] + red[1];
        if (i < 300) g_A[(size_t)b * NP * NP + i * NP + 300] = __float2half_rn(tot);
        else         g_C[b] = tot;
    }
}

// ---- projection: Ph[ph] (fp16) = X[B x K](fp32) @ W[K x NP] + bias;
//      ph==0 additionally writes exact fp32 proj_T to outT ----
__global__ void __launch_bounds__(256) k_proj(
    const float* __restrict__ X, int K, int wsel,
    const float* __restrict__ bias, int ph, float* __restrict__ outT)
{
    extern __shared__ __half sh[];
    __half* sA0 = sh;
    __half* sA1 = sh + PBM * SA_STR;
    __half* sB0 = sh + 2 * PBM * SA_STR;
    __half* sB1 = sB0 + PBK * SB_STR;
    const __half* W = wsel ? g_Wim : g_Wt;

    int tid = threadIdx.x, wid = tid >> 5, lane = tid & 31;
    int m0 = blockIdx.y * PBM, n0 = blockIdx.x * PBN;
    int wm = (wid >> 1) * 32, wn = (wid & 1) * 80;
    const float* Xb = X + (size_t)m0 * K;

    float acc[2][10][4];
    #pragma unroll
    for (int i = 0; i < 2; i++)
        #pragma unroll
        for (int f = 0; f < 10; f++)
            #pragma unroll
            for (int v = 0; v < 4; v++) acc[i][f][v] = 0.f;

    float4 xr[8];
    auto ldX = [&](int k0) {
        #pragma unroll
        for (int i = 0; i < 8; i++) {
            int idx = i * 256 + tid;           // 2048 float4 = 128 x 16
            int r = idx >> 4, c4 = idx & 15;
            xr[i] = *(const float4*)(Xb + (size_t)r * K + k0 + c4 * 4);
        }
    };
    auto stX = [&](__half* sA) {
        #pragma unroll
        for (int i = 0; i < 8; i++) {
            int idx = i * 256 + tid;
            int r = idx >> 4, c4 = idx & 15;
            __half2* d = (__half2*)(sA + r * SA_STR + c4 * 4);
            d[0] = __floats2half2_rn(xr[i].x, xr[i].y);
            d[1] = __floats2half2_rn(xr[i].z, xr[i].w);
        }
    };
    auto ldW = [&](__half* sB, int k0) {
        #pragma unroll
        for (int i = 0; i < 5; i++) {
            int idx = i * 256 + tid;           // 1280 int4 = 64 rows x 20
            int r = idx / 20, c = idx % 20;
            cp16(sB + r * SB_STR + c * 8, W + (size_t)(k0 + r) * NP + n0 + c * 8);
        }
    };

    ldX(0);
    ldW(sB0, 0); cpcommit();
    stX(sA0);
    cpwait0();
    __syncthreads();

    int nc = K >> 6;
    for (int c = 0; c < nc; c++) {
        __half* sAc = (c & 1) ? sA1 : sA0;
        __half* sBc = (c & 1) ? sB1 : sB0;
        __half* sAn = (c & 1) ? sA0 : sA1;
        __half* sBn = (c & 1) ? sB0 : sB1;
        bool more = (c + 1 < nc);
        if (more) { ldX((c + 1) * PBK); ldW(sBn, (c + 1) * PBK); cpcommit(); }
        #pragma unroll
        for (int kk = 0; kk < PBK; kk += 16) {
            uint32_t af[2][4];
            #pragma unroll
            for (int i = 0; i < 2; i++)
                ldsm4(af[i], su32(sAc + (wm + i*16 + (lane & 15)) * SA_STR + kk + ((lane >> 4) << 3)));
            #pragma unroll
            for (int j = 0; j < 5; j++) {
                uint32_t bf[4];
                ldsm4t(bf, su32(sBc + (kk + (lane & 15)) * SB_STR + wn + j*16 + ((lane >> 4) << 3)));
                #pragma unroll
                for (int i = 0; i < 2; i++) {
                    mma16816(acc[i][2*j],   af[i], bf);
                    mma16816(acc[i][2*j+1], af[i], bf + 2);
                }
            }
        }
        if (more) stX(sAn);
        cpwait0();
        __syncthreads();
    }

    int row = lane >> 2, colb = (lane & 3) * 2;
    __half* Ph = g_Ph[ph];
    #pragma unroll
    for (int i = 0; i < 2; i++)
        #pragma unroll
        for (int f = 0; f < 10; f++) {
            int cg = n0 + wn + f * 8 + colb;
            float b0 = (cg     < 300) ? bias[cg]     : 0.f;
            float b1 = (cg + 1 < 300) ? bias[cg + 1] : 0.f;
            #pragma unroll
            for (int h = 0; h < 2; h++) {
                int r = m0 + wm + i * 16 + row + h * 8;
                float v0 = acc[i][f][h*2]   + b0;
                float v1 = acc[i][f][h*2+1] + b1;
                *(__half2*)(Ph + (size_t)r * NP + cg) = __floats2half2_rn(v0, v1);
                if (outT) {
                    if (cg     < 300) outT[(size_t)r * 300 + cg]     = v0;
                    if (cg + 1 < 300) outT[(size_t)r * 300 + cg + 1] = v1;
                }
            }
        }
}

// ---- fused attention: quadratic forms + sigmoid + softmax + scaled outputs ----
__global__ void __launch_bounds__(256) k_attn(float* __restrict__ out) {
    extern __shared__ __half sm[];
    __half* sP0 = sm;
    __half* sP1 = sm + ATT_SP;
    __half* sAb = sm + 2 * ATT_SP;
    float*  sAl = (float*)(sm + 2 * ATT_SP + ATT_AB);

    int tid = threadIdx.x, wid = tid >> 5, lane = tid & 31;
    int m0 = blockIdx.x * 128;
    int wm = wid * 16;
    int row = lane >> 2, colb = (lane & 3) * 2;

    auto stageP = [&](int b, __half* dst) {
        __syncthreads();
        const __half* src = g_Ph[b] + (size_t)m0 * NP;
        #pragma unroll
        for (int i = 0; i < 20; i++) {
            int idx = i * 256 + tid;          // 5120 int4 = 128 rows x 40
            int r = idx / 40, c = idx % 40;
            cp16(dst + r * SP_STR + c * 8, src + (size_t)r * NP + c * 8);
        }
        cpcommit(); cpwait0();
        __syncthreads();
        if (tid < 128) dst[tid * SP_STR + 300] = __float2half_rn(1.f);   // u-trick
        __syncthreads();
    };

    auto quad = [&](const __half* sP, int b) {
        float aLo = 0.f, aHi = 0.f;
        const __half* Ab = g_A + (size_t)b * NP * NP;
        for (int nb = 0; nb < 5; nb++) {
            int n0 = nb * 64;
            __syncthreads();
            #pragma unroll
            for (int i = 0; i < 10; i++) {
                int idx = i * 256 + tid;      // 2560 int4 = 320 rows x 8
                int r = idx >> 3, c = idx & 7;
                cp16(sAb + r * SA_STR + c * 8, Ab + (size_t)r * NP + n0 + c * 8);
            }
            cpcommit(); cpwait0();
            __syncthreads();
            float acc[8][4];
            #pragma unroll
            for (int f = 0; f < 8; f++)
                #pragma unroll
                for (int v = 0; v < 4; v++) acc[f][v] = 0.f;
            #pragma unroll 4
            for (int kk = 0; kk < NP; kk += 16) {
                uint32_t af[4];
                ldsm4(af, su32(sP + (wm + (lane & 15)) * SP_STR + kk + ((lane >> 4) << 3)));
                #pragma unroll
                for (int j = 0; j < 4; j++) {
                    uint32_t bf[4];
                    ldsm4t(bf, su32(sAb + (kk + (lane & 15)) * SA_STR + j*16 + ((lane >> 4) << 3)));
                    mma16816(acc[2*j],   af, bf);
                    mma16816(acc[2*j+1], af, bf + 2);
                }
            }
            #pragma unroll
            for (int f = 0; f < 8; f++) {
                int c = n0 + f * 8 + colb;
                int r0 = wm + row, r1 = r0 + 8;
                aLo += acc[f][0] * __half2float(sP[r0 * SP_STR + c])
                     + acc[f][1] * __half2float(sP[r0 * SP_STR + c + 1]);
                aHi += acc[f][2] * __half2float(sP[r1 * SP_STR + c])
                     + acc[f][3] * __half2float(sP[r1 * SP_STR + c + 1]);
            }
        }
        aLo += __shfl_xor_sync(0xffffffffu, aLo, 1);
        aLo += __shfl_xor_sync(0xffffffffu, aLo, 2);
        aHi += __shfl_xor_sync(0xffffffffu, aHi, 1);
        aHi += __shfl_xor_sync(0xffffffffu, aHi, 2);
        if ((lane & 3) == 0) {
            sAl[b * 128 + wm + row]     = aLo;
            sAl[b * 128 + wm + 8 + row] = aHi;
        }
    };

    stageP(0, sP0); quad(sP0, 0);     // T
    stageP(1, sP0); quad(sP0, 1);     // IM (overwrites T tile; oT already written)
    stageP(2, sP1); quad(sP1, 2);     // CD
    __syncthreads();

    if (tid < 128) {
        float is = rsqrtf(300.f);
        float aT = (sAl[tid]       + g_C[0]) * is;
        float aI = (sAl[128 + tid] + g_C[1]) * is;
        float aC = (sAl[256 + tid] + g_C[2]) * is;
        float zT = 1.f / (1.f + expf(-aT));
        float zI = 1.f / (1.f + expf(-aI));
        float zC = 1.f / (1.f + expf(-aC));
        float mI = zI * zT, mC = zC * zT;
        float mx = fmaxf(mI, mC);
        float e0 = expf(mI - mx), e1 = expf(mC - mx);
        float inv = 1.f / (e0 + e1);
        sAl[tid]       = e0 * inv;    // a0
        sAl[128 + tid] = e1 * inv;    // a1
    }
    __syncthreads();

    for (int r = wid; r < 128; r += 8) {
        float a0 = sAl[r], a1 = sAl[128 + r];
        size_t gr = m0 + r;
        float* oI = out + ((size_t)BATCH     + gr) * 300;
        float* oC = out + ((size_t)2 * BATCH + gr) * 300;
        for (int c = lane; c < 300; c += 32) {
            oI[c] = a0 * __half2float(sP0[r * SP_STR + c]);
            oC[c] = a1 * __half2float(sP1[r * SP_STR + c]);
        }
    }
}

extern "C" void kernel_launch(void* const* d_in, const int* in_sizes, int n_in,
                              void* d_out, int out_size) {
    const float* T   = (const float*)d_in[0];
    const float* IM  = (const float*)d_in[1];
    const float* CD  = (const float*)d_in[2];
    const float* Wt  = (const float*)d_in[3];
    const float* bt  = (const float*)d_in[4];
    const float* Wim = (const float*)d_in[5];
    const float* bim = (const float*)d_in[6];
    float* out = (float*)d_out;

    static int inited = 0;
    if (!inited) {
        cudaFuncSetAttribute(k_proj, cudaFuncAttributeMaxDynamicSharedMemorySize, PROJ_SMEM);
        cudaFuncSetAttribute(k_attn, cudaFuncAttributeMaxDynamicSharedMemorySize, ATT_SMEM);
        inited = 1;
    }

    k_convW<<<(768  * NP + 255) / 256, 256>>>(Wt,  0, 768);
    k_convW<<<(2048 * NP + 255) / 256, 256>>>(Wim, 1, 2048);

    dim3 b16(16, 16), g3(NP / 16, NP / 16, 3);
    k_prepA<<<g3, b16>>>((const float*)d_in[7],  (const float*)d_in[9],
                         (const float*)d_in[11], (const float*)d_in[13],
                         (const float*)d_in[15], (const float*)d_in[17]);
    k_u<<<dim3(301, 3), 64>>>(
        (const float*)d_in[7],  (const float*)d_in[9],  (const float*)d_in[8],  (const float*)d_in[10],
        (const float*)d_in[11], (const float*)d_in[13], (const float*)d_in[12], (const float*)d_in[14],
        (const float*)d_in[15], (const float*)d_in[17], (const float*)d_in[16], (const float*)d_in[18]);

    dim3 gg(2, BATCH / PBM);
    k_proj<<<gg, 256, PROJ_SMEM>>>(T,  768,  0, bt,  0, out);      // proj_T (+ exact fp32 oT)
    k_proj<<<gg, 256, PROJ_SMEM>>>(IM, 2048, 1, bim, 1, nullptr);  // proj_IM
    k_proj<<<gg, 256, PROJ_SMEM>>>(CD, 768,  0, bt,  2, nullptr);  // proj_CD

    k_attn<<<BATCH / 128, 256, ATT_SMEM>>>(out);
}

// round 7
// speedup vs baseline: 1.8386x; 1.0530x over previous
#include <cuda_runtime.h>
#include <cuda_fp16.h>
#include <cstdint>

#define BATCH 65536
#define NP 320

// proj GEMM tiling: 128 x 320, K-chunk 64, 512 threads (16 warps, 4M x 4N)
#define PBM 128
#define PBK 64
#define SA_STR 72     // 64 + 8 pad (halves)
#define SB_STR 328    // 320 + 8 pad (halves)
#define PROJ_SMEM ((2*(PBM*SA_STR + PBK*SB_STR)) * 2)     // 120832 B

// attention kernel: one P tile + double-buffered A tiles
#define SP_STR 328
#define ATT_SMEM ((128*SP_STR + 2*NP*SA_STR) * 2 + 384*4) // 177664 B

__device__ __align__(16) __half g_Wt [768  * NP];
__device__ __align__(16) __half g_Wim[2048 * NP];
__device__ __align__(16) __half g_A  [3 * NP * NP];
__device__ float g_C[3];
__device__ __align__(16) __half g_Ph[3][(size_t)BATCH * NP];

static __device__ __forceinline__ uint32_t su32(const void* p) {
    return (uint32_t)__cvta_generic_to_shared(p);
}
static __device__ __forceinline__ void cp16(__half* dst, const __half* src) {
    asm volatile("cp.async.cg.shared.global [%0], [%1], 16;\n" :: "r"(su32(dst)), "l"(src));
}
static __device__ __forceinline__ void cpcommit() { asm volatile("cp.async.commit_group;\n"); }
static __device__ __forceinline__ void cpwait0()  { asm volatile("cp.async.wait_group 0;\n"); }
static __device__ __forceinline__ void cpwait1()  { asm volatile("cp.async.wait_group 1;\n"); }
static __device__ __forceinline__ void ldsm4(uint32_t* r, uint32_t a) {
    asm volatile("ldmatrix.sync.aligned.m8n8.x4.shared.b16 {%0,%1,%2,%3}, [%4];\n"
                 : "=r"(r[0]), "=r"(r[1]), "=r"(r[2]), "=r"(r[3]) : "r"(a));
}
static __device__ __forceinline__ void ldsm4t(uint32_t* r, uint32_t a) {
    asm volatile("ldmatrix.sync.aligned.m8n8.x4.trans.shared.b16 {%0,%1,%2,%3}, [%4];\n"
                 : "=r"(r[0]), "=r"(r[1]), "=r"(r[2]), "=r"(r[3]) : "r"(a));
}
static __device__ __forceinline__ void mma16816(float* c, const uint32_t* a, const uint32_t* b) {
    asm volatile("mma.sync.aligned.m16n8k16.row.col.f32.f16.f16.f32 "
                 "{%0,%1,%2,%3}, {%4,%5,%6,%7}, {%8,%9}, {%0,%1,%2,%3};\n"
                 : "+f"(c[0]), "+f"(c[1]), "+f"(c[2]), "+f"(c[3])
                 : "r"(a[0]), "r"(a[1]), "r"(a[2]), "r"(a[3]), "r"(b[0]), "r"(b[1]));
}

// ---- convert weight [K x 300] fp32 -> [K x NP] fp16 (zero-padded) ----
__global__ void k_convW(const float* __restrict__ src, int which, int K) {
    __half* dst = which ? g_Wim : g_Wt;
    int i = blockIdx.x * 256 + threadIdx.x;
    if (i < K * NP) {
        int k = i / NP, n = i - k * NP;
        dst[i] = __float2half_rn(n < 300 ? src[k * 300 + n] : 0.f);
    }
}

// ---- A[b][i][j] = Wq[i,:]·Wk[j,:]  (i,j<300 else 0); 32x32 blocks, 2x2/thread ----
__global__ void k_prepA(const float* __restrict__ Wq0, const float* __restrict__ Wk0,
                        const float* __restrict__ Wq1, const float* __restrict__ Wk1,
                        const float* __restrict__ Wq2, const float* __restrict__ Wk2) {
    int b = blockIdx.z;
    const float* Wq = (b == 0) ? Wq0 : (b == 1) ? Wq1 : Wq2;
    const float* Wk = (b == 0) ? Wk0 : (b == 1) ? Wk1 : Wk2;
    __shared__ float sq[32][17], sk[32][17];
    int tx = threadIdx.x, ty = threadIdx.y;
    int tid = ty * 16 + tx;
    int i0 = blockIdx.y * 32, j0 = blockIdx.x * 32;
    float a00 = 0.f, a01 = 0.f, a10 = 0.f, a11 = 0.f;
    for (int o0 = 0; o0 < 304; o0 += 16) {
        #pragma unroll
        for (int e = 0; e < 2; e++) {
            int idx = e * 256 + tid;
            int r = idx >> 4, c = idx & 15;
            int o = o0 + c;
            sq[r][c] = (i0 + r < 300 && o < 300) ? Wq[(i0 + r) * 300 + o] : 0.f;
            sk[r][c] = (j0 + r < 300 && o < 300) ? Wk[(j0 + r) * 300 + o] : 0.f;
        }
        __syncthreads();
        #pragma unroll
        for (int t = 0; t < 16; t++) {
            float q0 = sq[2*ty][t],   q1 = sq[2*ty+1][t];
            float k0 = sk[2*tx][t],   k1 = sk[2*tx+1][t];
            a00 += q0 * k0; a01 += q0 * k1;
            a10 += q1 * k0; a11 += q1 * k1;
        }
        __syncthreads();
    }
    size_t base = (size_t)b * NP * NP;
    int i = i0 + 2 * ty, j = j0 + 2 * tx;
    g_A[base + (i  ) * NP + j    ] = __float2half_rn((i   < 300 && j   < 300) ? a00 : 0.f);
    g_A[base + (i  ) * NP + j + 1] = __float2half_rn((i   < 300 && j+1 < 300) ? a01 : 0.f);
    g_A[base + (i+1) * NP + j    ] = __float2half_rn((i+1 < 300 && j   < 300) ? a10 : 0.f);
    g_A[base + (i+1) * NP + j + 1] = __float2half_rn((i+1 < 300 && j+1 < 300) ? a11 : 0.f);
}

// ---- u_i = Wq[i]·bk + Wk[i]·bq -> A[b][i][300];  block i==300: c=bq·bk ----
__global__ void k_u(const float* __restrict__ Wq0, const float* __restrict__ Wk0,
                    const float* __restrict__ bq0, const float* __restrict__ bk0,
                    const float* __restrict__ Wq1, const float* __restrict__ Wk1,
                    const float* __restrict__ bq1, const float* __restrict__ bk1,
                    const float* __restrict__ Wq2, const float* __restrict__ Wk2,
                    const float* __restrict__ bq2, const float* __restrict__ bk2) {
    int b = blockIdx.y;
    const float* Wq = (b == 0) ? Wq0 : (b == 1) ? Wq1 : Wq2;
    const float* Wk = (b == 0) ? Wk0 : (b == 1) ? Wk1 : Wk2;
    const float* bq = (b == 0) ? bq0 : (b == 1) ? bq1 : bq2;
    const float* bk = (b == 0) ? bk0 : (b == 1) ? bk1 : bk2;
    __shared__ float red[2];
    int i = blockIdx.x, tid = threadIdx.x;
    float s = 0.f;
    if (i < 300) { for (int o = tid; o < 300; o += 64) s += Wq[i*300+o]*bk[o] + Wk[i*300+o]*bq[o]; }
    else         { for (int o = tid; o < 300; o += 64) s += bq[o]*bk[o]; }
    #pragma unroll
    for (int o = 16; o; o >>= 1) s += __shfl_xor_sync(0xffffffffu, s, o);
    if ((tid & 31) == 0) red[tid >> 5] = s;
    __syncthreads();
    if (tid == 0) {
        float tot = red[0] + red[1];
        if (i < 300) g_A[(size_t)b * NP * NP + i * NP + 300] = __float2half_rn(tot);
        else         g_C[b] = tot;
    }
}

// ---- projection: Ph[ph] (fp16) = X[B x K](fp32) @ W[K x NP] + bias  (single N pass)
//      ph==0 additionally writes exact fp32 proj_T to outT ----
__global__ void __launch_bounds__(512) k_proj(
    const float* __restrict__ X0, const float* __restrict__ X1,
    int K, int wsel, const float* __restrict__ bias,
    int ph0, int ph1, float* __restrict__ outT, int nsplit)
{
    extern __shared__ __half sh[];
    __half* sA0 = sh;
    __half* sA1 = sh + PBM * SA_STR;
    __half* sB0 = sh + 2 * PBM * SA_STR;
    __half* sB1 = sB0 + PBK * SB_STR;
    const __half* W = wsel ? g_Wim : g_Wt;

    int by = blockIdx.y;
    bool sel = (by >= nsplit);
    const float* X = sel ? X1 : X0;
    int ph = sel ? ph1 : ph0;
    int m0 = (sel ? by - nsplit : by) * PBM;

    int tid = threadIdx.x, wid = tid >> 5, lane = tid & 31;
    int wm = (wid >> 2) * 32, wn = (wid & 3) * 80;
    const float* Xb = X + (size_t)m0 * K;

    float acc[2][10][4];
    #pragma unroll
    for (int i = 0; i < 2; i++)
        #pragma unroll
        for (int f = 0; f < 10; f++)
            #pragma unroll
            for (int v = 0; v < 4; v++) acc[i][f][v] = 0.f;

    float4 xr[4];
    auto ldX = [&](int k0) {
        #pragma unroll
        for (int i = 0; i < 4; i++) {
            int idx = i * 512 + tid;           // 2048 float4 = 128 rows x 16
            int r = idx >> 4, c4 = idx & 15;
            xr[i] = *(const float4*)(Xb + (size_t)r * K + k0 + c4 * 4);
        }
    };
    auto stX = [&](__half* sA) {
        #pragma unroll
        for (int i = 0; i < 4; i++) {
            int idx = i * 512 + tid;
            int r = idx >> 4, c4 = idx & 15;
            __half2* d = (__half2*)(sA + r * SA_STR + c4 * 4);
            d[0] = __floats2half2_rn(xr[i].x, xr[i].y);
            d[1] = __floats2half2_rn(xr[i].z, xr[i].w);
        }
    };
    auto ldW = [&](__half* sB, int k0) {
        #pragma unroll
        for (int i = 0; i < 5; i++) {
            int idx = i * 512 + tid;           // 2560 int4 = 64 rows x 40
            int r = idx / 40, c = idx - r * 40;
            cp16(sB + r * SB_STR + c * 8, W + (size_t)(k0 + r) * NP + c * 8);
        }
    };

    ldX(0);
    ldW(sB0, 0); cpcommit();
    stX(sA0);
    cpwait0();
    __syncthreads();

    int nc = K >> 6;
    for (int c = 0; c < nc; c++) {
        __half* sAc = (c & 1) ? sA1 : sA0;
        __half* sBc = (c & 1) ? sB1 : sB0;
        __half* sAn = (c & 1) ? sA0 : sA1;
        __half* sBn = (c & 1) ? sB0 : sB1;
        bool more = (c + 1 < nc);
        if (more) { ldX((c + 1) * PBK); ldW(sBn, (c + 1) * PBK); cpcommit(); }
        #pragma unroll
        for (int kk = 0; kk < PBK; kk += 16) {
            uint32_t af[2][4];
            #pragma unroll
            for (int i = 0; i < 2; i++)
                ldsm4(af[i], su32(sAc + (wm + i*16 + (lane & 15)) * SA_STR + kk + ((lane >> 4) << 3)));
            #pragma unroll
            for (int j = 0; j < 5; j++) {
                uint32_t bf[4];
                ldsm4t(bf, su32(sBc + (kk + (lane & 15)) * SB_STR + wn + j*16 + ((lane >> 4) << 3)));
                #pragma unroll
                for (int i = 0; i < 2; i++) {
                    mma16816(acc[i][2*j],   af[i], bf);
                    mma16816(acc[i][2*j+1], af[i], bf + 2);
                }
            }
        }
        if (more) stX(sAn);
        cpwait0();
        __syncthreads();
    }

    int row = lane >> 2, colb = (lane & 3) * 2;
    __half* Ph = g_Ph[ph];
    #pragma unroll
    for (int i = 0; i < 2; i++)
        #pragma unroll
        for (int f = 0; f < 10; f++) {
            int cg = wn + f * 8 + colb;
            float b0 = (cg     < 300) ? bias[cg]     : 0.f;
            float b1 = (cg + 1 < 300) ? bias[cg + 1] : 0.f;
            #pragma unroll
            for (int h = 0; h < 2; h++) {
                int r = m0 + wm + i * 16 + row + h * 8;
                float v0 = acc[i][f][h*2]   + b0;
                float v1 = acc[i][f][h*2+1] + b1;
                *(__half2*)(Ph + (size_t)r * NP + cg) = __floats2half2_rn(v0, v1);
                if (ph == 0) {
                    if (cg     < 300) outT[(size_t)r * 300 + cg]     = v0;
                    if (cg + 1 < 300) outT[(size_t)r * 300 + cg + 1] = v1;
                }
            }
        }
}

// ---- fused attention: quadratic forms + sigmoid + softmax + scaled outputs ----
__global__ void __launch_bounds__(256) k_attn(float* __restrict__ out) {
    extern __shared__ __half sm[];
    __half* sP  = sm;                               // 128 x SP_STR
    __half* sAb[2] = { sm + 128 * SP_STR, sm + 128 * SP_STR + NP * SA_STR };
    float*  sAl = (float*)(sm + 128 * SP_STR + 2 * NP * SA_STR);

    int tid = threadIdx.x, wid = tid >> 5, lane = tid & 31;
    int m0 = blockIdx.x * 128;
    int wm = wid * 16;
    int row = lane >> 2, colb = (lane & 3) * 2;

    auto stageP = [&](int b) {
        const __half* src = g_Ph[b] + (size_t)m0 * NP;
        #pragma unroll
        for (int i = 0; i < 20; i++) {
            int idx = i * 256 + tid;          // 5120 int4 = 128 rows x 40
            int r = idx / 40, c = idx - r * 40;
            cp16(sP + r * SP_STR + c * 8, src + (size_t)r * NP + c * 8);
        }
        cpcommit(); cpwait0();
        __syncthreads();
        if (tid < 128) sP[tid * SP_STR + 300] = __float2half_rn(1.f);   // u-trick
        __syncthreads();
    };
    auto prefA = [&](int s, int buf) {
        int b = s / 5, nb = s - b * 5;
        const __half* Ab = g_A + (size_t)b * NP * NP + nb * 64;
        __half* dst = sAb[buf];
        #pragma unroll
        for (int i = 0; i < 10; i++) {
            int idx = i * 256 + tid;          // 2560 int4 = 320 rows x 8
            int r = idx >> 3, c = idx & 7;
            cp16(dst + r * SA_STR + c * 8, Ab + (size_t)r * NP + c * 8);
        }
        cpcommit();
    };

    float aLo = 0.f, aHi = 0.f;
    stageP(0);
    prefA(0, 0);

    for (int s = 0; s < 15; s++) {
        int b = s / 5, nb = s - b * 5;
        if (nb == 0 && s > 0) {
            __syncthreads();
            stageP(b);
        }
        __syncthreads();
        if (s < 14) prefA(s + 1, (s + 1) & 1);
        if (s < 14) cpwait1(); else cpwait0();
        __syncthreads();

        const __half* Ab = sAb[s & 1];
        float accq[8][4];
        #pragma unroll
        for (int f = 0; f < 8; f++)
            #pragma unroll
            for (int v = 0; v < 4; v++) accq[f][v] = 0.f;
        #pragma unroll 5
        for (int kk = 0; kk < NP; kk += 16) {
            uint32_t af[4];
            ldsm4(af, su32(sP + (wm + (lane & 15)) * SP_STR + kk + ((lane >> 4) << 3)));
            #pragma unroll
            for (int j = 0; j < 4; j++) {
                uint32_t bf[4];
                ldsm4t(bf, su32(Ab + (kk + (lane & 15)) * SA_STR + j*16 + ((lane >> 4) << 3)));
                mma16816(accq[2*j],   af, bf);
                mma16816(accq[2*j+1], af, bf + 2);
            }
        }
        int r0 = wm + row, r1 = wm + 8 + row;
        #pragma unroll
        for (int f = 0; f < 8; f++) {
            int c = nb * 64 + f * 8 + colb;
            aLo += accq[f][0] * __half2float(sP[r0 * SP_STR + c])
                 + accq[f][1] * __half2float(sP[r0 * SP_STR + c + 1]);
            aHi += accq[f][2] * __half2float(sP[r1 * SP_STR + c])
                 + accq[f][3] * __half2float(sP[r1 * SP_STR + c + 1]);
        }
        if (nb == 4) {
            aLo += __shfl_xor_sync(0xffffffffu, aLo, 1);
            aLo += __shfl_xor_sync(0xffffffffu, aLo, 2);
            aHi += __shfl_xor_sync(0xffffffffu, aHi, 1);
            aHi += __shfl_xor_sync(0xffffffffu, aHi, 2);
            if ((lane & 3) == 0) {
                sAl[b * 128 + wm + row]     = aLo;
                sAl[b * 128 + wm + 8 + row] = aHi;
            }
            aLo = 0.f; aHi = 0.f;
        }
    }
    __syncthreads();

    if (tid < 128) {
        float is = rsqrtf(300.f);
        float aT = (sAl[tid]       + g_C[0]) * is;
        float aI = (sAl[128 + tid] + g_C[1]) * is;
        float aC = (sAl[256 + tid] + g_C[2]) * is;
        float zT = 1.f / (1.f + expf(-aT));
        float zI = 1.f / (1.f + expf(-aI));
        float zC = 1.f / (1.f + expf(-aC));
        float mI = zI * zT, mC = zC * zT;
        float mx = fmaxf(mI, mC);
        float e0 = expf(mI - mx), e1 = expf(mC - mx);
        float inv = 1.f / (e0 + e1);
        sAl[tid]       = e0 * inv;    // weight for IM
        sAl[128 + tid] = e1 * inv;    // weight for CD
    }
    __syncthreads();

    // outputs: oC from sP (holds CD), oI re-read from g_Ph[1]
    for (int r = wid; r < 128; r += 8) {
        float a0 = sAl[r], a1 = sAl[128 + r];
        const __half* pI = g_Ph[1] + (size_t)(m0 + r) * NP;
        float* oI = out + ((size_t)BATCH     + m0 + r) * 300;
        float* oC = out + ((size_t)2 * BATCH + m0 + r) * 300;
        for (int h = lane; h < 150; h += 32) {
            float2 fI = __half22float2(*(const __half2*)(pI + 2 * h));
            float2 fC = __half22float2(*(const __half2*)(sP + r * SP_STR + 2 * h));
            float2 vI; vI.x = a0 * fI.x; vI.y = a0 * fI.y;
            float2 vC; vC.x = a1 * fC.x; vC.y = a1 * fC.y;
            *(float2*)(oI + 2 * h) = vI;
            *(float2*)(oC + 2 * h) = vC;
        }
    }
}

extern "C" void kernel_launch(void* const* d_in, const int* in_sizes, int n_in,
                              void* d_out, int out_size) {
    const float* T   = (const float*)d_in[0];
    const float* IM  = (const float*)d_in[1];
    const float* CD  = (const float*)d_in[2];
    const float* Wt  = (const float*)d_in[3];
    const float* bt  = (const float*)d_in[4];
    const float* Wim = (const float*)d_in[5];
    const float* bim = (const float*)d_in[6];
    float* out = (float*)d_out;

    cudaFuncSetAttribute(k_proj, cudaFuncAttributeMaxDynamicSharedMemorySize, PROJ_SMEM);
    cudaFuncSetAttribute(k_attn, cudaFuncAttributeMaxDynamicSharedMemorySize, ATT_SMEM);

    k_convW<<<(768  * NP + 255) / 256, 256>>>(Wt,  0, 768);
    k_convW<<<(2048 * NP + 255) / 256, 256>>>(Wim, 1, 2048);

    k_prepA<<<dim3(10, 10, 3), dim3(16, 16)>>>(
        (const float*)d_in[7],  (const float*)d_in[9],
        (const float*)d_in[11], (const float*)d_in[13],
        (const float*)d_in[15], (const float*)d_in[17]);
    k_u<<<dim3(301, 3), 64>>>(
        (const float*)d_in[7],  (const float*)d_in[9],  (const float*)d_in[8],  (const float*)d_in[10],
        (const float*)d_in[11], (const float*)d_in[13], (const float*)d_in[12], (const float*)d_in[14],
        (const float*)d_in[15], (const float*)d_in[17], (const float*)d_in[16], (const float*)d_in[18]);

    // T + CD share Wt: one launch, first 512 blocks = T (writes oT), next 512 = CD
    k_proj<<<dim3(1, 1024), 512, PROJ_SMEM>>>(T, CD, 768, 0, bt, 0, 2, out, 512);
    k_proj<<<dim3(1, 512),  512, PROJ_SMEM>>>(IM, IM, 2048, 1, bim, 1, 1, nullptr, 512);

    k_attn<<<BATCH / 128, 256, ATT_SMEM>>>(out);
}